// round 14
// baseline (speedup 1.0000x reference)
#include <cuda_runtime.h>
#include <math.h>
#include <stdint.h>

#define NT 256
#define NW 8

// ---------------- scratch (device globals, no allocation) ----------------
__device__ float g_P[4194304];     // split-K partials, transposed [bk][c][32]
__device__ float g_qkv[98304];     // fused q/k/v outputs [3][32][1024]
__device__ float g_qe[32768];
__device__ float g_attn_s[32768];
__device__ float g_attn_e[32768];
__device__ float g_x1[32768];
__device__ float g_x2[32768];
__device__ float g_h[131072];      // ffn hidden [32,4096]
__device__ float g_row[32768];     // reduced (pre-LN) rows

// ---------------- warp-broadcast GEMM: C[32,N] = A[32,K] @ W ----------------
// lane = batch row (M=32 == warpsize). Each warp owns 8 columns; W is loaded
// by uniform-address LDG.128 (one wavefront, zero redundancy), A comes from a
// k-major padded smem tile (conflict-free). Partials stored TRANSPOSED:
// P[bk][c][32] so lane-stride-1 stores coalesce.
// headed=1: W is [H][K][64], n-tile bn == head. headed=0: W is [K][N].
template<int KC>
__device__ __forceinline__ void gemm_core(const float* __restrict__ A,
                                          const float* __restrict__ W,
                                          float* __restrict__ P,
                                          int K, int N, int headed,
                                          int bn, int bk)
{
    __shared__ float At[KC * 33];              // [k][b], pad 33 vs bank conflicts
    int tid = threadIdx.x, lane = tid & 31, w = tid >> 5;
    int k0 = bk * KC;

    // fill A tile k-major (coalesced read, conflict-free write), one barrier
    #pragma unroll
    for (int i = tid; i < 32 * KC; i += NT) {
        int b = i / KC, kk = i - b * KC;
        At[kk * 33 + b] = A[(size_t)b * K + k0 + kk];
    }
    __syncthreads();

    int c0 = w * 8;
    const float* Wp;
    size_t ldw;
    if (headed) { Wp = W + (size_t)bn * K * 64 + (size_t)k0 * 64 + c0; ldw = 64; }
    else        { Wp = W + (size_t)k0 * N + bn * 64 + c0;              ldw = (size_t)N; }

    float acc[8];
    #pragma unroll
    for (int j = 0; j < 8; j++) acc[j] = 0.f;

    #pragma unroll 2
    for (int k4 = 0; k4 < KC; k4 += 4) {
        float4 wa[4], wb[4];
        #pragma unroll
        for (int j = 0; j < 4; j++) {
            const float* p = Wp + (size_t)(k4 + j) * ldw;
            wa[j] = *reinterpret_cast<const float4*>(p);
            wb[j] = *reinterpret_cast<const float4*>(p + 4);
        }
        float a[4];
        #pragma unroll
        for (int j = 0; j < 4; j++) a[j] = At[(k4 + j) * 33 + lane];
        #pragma unroll
        for (int j = 0; j < 4; j++) {
            acc[0] += a[j] * wa[j].x; acc[1] += a[j] * wa[j].y;
            acc[2] += a[j] * wa[j].z; acc[3] += a[j] * wa[j].w;
            acc[4] += a[j] * wb[j].x; acc[5] += a[j] * wb[j].y;
            acc[6] += a[j] * wb[j].z; acc[7] += a[j] * wb[j].w;
        }
    }
    float* dst = P + (size_t)bk * N * 32 + (size_t)(bn * 64 + c0) * 32 + lane;
    #pragma unroll
    for (int j = 0; j < 8; j++) dst[j * 32] = acc[j];
}

__global__ void __launch_bounds__(NT, 4)
gemm_k64(const float* __restrict__ A, const float* __restrict__ W,
         float* __restrict__ P, int K, int N, int headed)
{
    gemm_core<64>(A, W, P, K, N, headed, blockIdx.x, blockIdx.y);
}

__global__ void __launch_bounds__(NT, 4)
gemm_k128(const float* __restrict__ A, const float* __restrict__ W,
          float* __restrict__ P, int K, int N, int headed)
{
    gemm_core<128>(A, W, P, K, N, headed, blockIdx.x, blockIdx.y);
}

// fused q/k/v: z selects weight & partial slab (8 splits x 32768 each).
__global__ void __launch_bounds__(NT, 4)
gemm_qkv(const float* __restrict__ A,
         const float* __restrict__ W0,
         const float* __restrict__ W1,
         const float* __restrict__ W2,
         float* __restrict__ P)
{
    int z = blockIdx.z;
    const float* W = (z == 0) ? W0 : (z == 1) ? W1 : W2;
    gemm_core<128>(A, W, P + (size_t)z * 262144, 1024, 1024, 1,
                   blockIdx.x, blockIdx.y);
}

// ---------------- reducers over TRANSPOSED partials P[s][c][32] -----------
__global__ void reduce_qkv(const float* __restrict__ P, float* __restrict__ out)
{
    int i = blockIdx.x * blockDim.x + threadIdx.x;   // 98304: [z][b][c]
    int z = i >> 15, r = i & 32767;
    int b = r >> 10, c = r & 1023;
    const float* p = P + (size_t)z * 262144 + c * 32 + b;
    float v = 0.f;
    #pragma unroll
    for (int s = 0; s < 8; s++) v += p[(size_t)s * 32768];
    out[i] = v;
}

__global__ void reduce_sum_t(const float* __restrict__ P, float* __restrict__ out,
                             int KS)
{
    int i = blockIdx.x * blockDim.x + threadIdx.x;   // 32768: [b][c]
    int b = i >> 10, c = i & 1023;
    const float* p = P + c * 32 + b;
    float v = 0.f;
    for (int s = 0; s < KS; s++) v += p[(size_t)s * 32768];
    out[i] = v;
}

// ffn1 reduce: total 131072 = [b][4096]
__global__ void reduce_bias_relu_t(const float* __restrict__ P,
                                   const float* __restrict__ bias,
                                   float* __restrict__ out, int KS)
{
    int i = blockIdx.x * blockDim.x + threadIdx.x;
    int b = i >> 12, c = i & 4095;
    const float* p = P + c * 32 + b;
    float v = bias[c];
    for (int s = 0; s < KS; s++) v += p[(size_t)s * 131072];
    out[i] = fmaxf(v, 0.f);
}

// sum partials + bias + residual -> row buffer
__global__ void reduce_addres_t(const float* __restrict__ P, int KS,
                                const float* __restrict__ bias,
                                const float* __restrict__ res,
                                float* __restrict__ out)
{
    int i = blockIdx.x * blockDim.x + threadIdx.x;   // 32768
    int b = i >> 10, c = i & 1023;
    const float* p = P + c * 32 + b;
    float v = bias[c] + res[i];
    for (int s = 0; s < KS; s++) v += p[(size_t)s * 32768];
    out[i] = v;
}

// ---------------- LayerNorm over pre-reduced rows ----------------
__global__ void ln_norm(const float* __restrict__ row,
                        const float* __restrict__ gam, const float* __restrict__ bet,
                        float* __restrict__ out)
{
    __shared__ float redm[NW], redv[NW];
    __shared__ float sh_mean, sh_rstd;
    int b = blockIdx.x, tid = threadIdx.x, lane = tid & 31, wid = tid >> 5;
    const float* r = row + (size_t)b * 1024;
    float lsum = 0.f, lsq = 0.f;
    float vals[4];
    #pragma unroll
    for (int j = 0; j < 4; j++) {
        float v = r[tid + j * NT];
        vals[j] = v;
        lsum += v; lsq += v * v;
    }
    #pragma unroll
    for (int o = 16; o; o >>= 1) {
        lsum += __shfl_xor_sync(0xffffffffu, lsum, o);
        lsq  += __shfl_xor_sync(0xffffffffu, lsq, o);
    }
    if (!lane) { redm[wid] = lsum; redv[wid] = lsq; }
    __syncthreads();
    if (wid == 0) {
        float a  = (lane < NW) ? redm[lane] : 0.f;
        float c2 = (lane < NW) ? redv[lane] : 0.f;
        #pragma unroll
        for (int o = 4; o; o >>= 1) {
            a  += __shfl_xor_sync(0xffffffffu, a, o);
            c2 += __shfl_xor_sync(0xffffffffu, c2, o);
        }
        if (!lane) {
            float mean = a * (1.f / 1024.f);
            float var  = c2 * (1.f / 1024.f) - mean * mean;
            sh_mean = mean;
            sh_rstd = rsqrtf(var + 1e-6f);
        }
    }
    __syncthreads();
    float mean = sh_mean, rstd = sh_rstd;
    #pragma unroll
    for (int j = 0; j < 4; j++) {
        int c = tid + j * NT;
        out[(size_t)b * 1024 + c] = (vals[j] - mean) * rstd * gam[c] + bet[c];
    }
}

// ---------------- attention: one block per (b,h), float4 streaming -------
__global__ void attn_kernel(const float* __restrict__ q,
                            const float* __restrict__ Kc,
                            const float* __restrict__ Vc,
                            const float* __restrict__ knew,
                            const float* __restrict__ vnew,
                            const uint8_t* __restrict__ mask,
                            float* __restrict__ probs,
                            float* __restrict__ outv,
                            int T, int Tc)
{
    __shared__ float s[2048];
    __shared__ float red[NW];
    __shared__ float4 red4[256];
    __shared__ float sh_max, sh_sum;
    int bh = blockIdx.x, b = bh >> 4, h = bh & 15;
    int tid = threadIdx.x, lane = tid & 31, wid = tid >> 5;
    size_t base = (size_t)bh * Tc * 64;
    const uint8_t* mrow = mask + (size_t)b * T;
    float4 q4 = reinterpret_cast<const float4*>(q + (size_t)bh * 64)[lane & 15];

    // ---- K phase: warp covers 2 rows per float4 load, 8 rows in flight ----
    float lmax = -INFINITY;
    int half = lane >> 4;
    for (int t0 = wid * 8; t0 < Tc; t0 += NW * 8) {
        float d[4];
        #pragma unroll
        for (int j = 0; j < 4; j++) {
            int r = t0 + 2 * j;
            float4 kv = make_float4(0.f, 0.f, 0.f, 0.f);
            if (r + half < Tc)
                kv = reinterpret_cast<const float4*>(Kc + base + (size_t)r * 64)[lane];
            d[j] = kv.x * q4.x + kv.y * q4.y + kv.z * q4.z + kv.w * q4.w;
        }
        #pragma unroll
        for (int j = 0; j < 4; j++) {
            float v = d[j];
            v += __shfl_xor_sync(0xffffffffu, v, 8);
            v += __shfl_xor_sync(0xffffffffu, v, 4);
            v += __shfl_xor_sync(0xffffffffu, v, 2);
            v += __shfl_xor_sync(0xffffffffu, v, 1);
            int r = t0 + 2 * j + half;
            if ((lane & 15) == 0 && r < Tc) {
                float sc = v * 0.125f;
                if (mrow[r]) sc = -INFINITY;
                s[r] = sc;
                lmax = fmaxf(lmax, sc);
            }
        }
    }
    if (knew && wid == 0) {
        float4 kv = reinterpret_cast<const float4*>(knew + (size_t)bh * 64)[lane & 15];
        float v = kv.x * q4.x + kv.y * q4.y + kv.z * q4.z + kv.w * q4.w;
        v += __shfl_xor_sync(0xffffffffu, v, 8);
        v += __shfl_xor_sync(0xffffffffu, v, 4);
        v += __shfl_xor_sync(0xffffffffu, v, 2);
        v += __shfl_xor_sync(0xffffffffu, v, 1);
        if (lane == 0) {
            float sc = v * 0.125f;
            if (mrow[Tc]) sc = -INFINITY;
            s[Tc] = sc;
            lmax = fmaxf(lmax, sc);
        }
    }
    #pragma unroll
    for (int o = 16; o; o >>= 1) lmax = fmaxf(lmax, __shfl_xor_sync(0xffffffffu, lmax, o));
    if (lane == 0) red[wid] = lmax;
    __syncthreads();
    if (wid == 0) {
        float m = (lane < NW) ? red[lane] : -INFINITY;
        #pragma unroll
        for (int o = 4; o; o >>= 1) m = fmaxf(m, __shfl_xor_sync(0xffffffffu, m, o));
        if (lane == 0) sh_max = m;
    }
    __syncthreads();
    float gmax = sh_max;

    float lsum = 0.f;
    for (int t = tid; t < T; t += NT) {
        float e = __expf(s[t] - gmax);
        s[t] = e;
        lsum += e;
    }
    #pragma unroll
    for (int o = 16; o; o >>= 1) lsum += __shfl_xor_sync(0xffffffffu, lsum, o);
    if (lane == 0) red[wid] = lsum;
    __syncthreads();
    if (wid == 0) {
        float m = (lane < NW) ? red[lane] : 0.f;
        #pragma unroll
        for (int o = 4; o; o >>= 1) m += __shfl_xor_sync(0xffffffffu, m, o);
        if (lane == 0) sh_sum = m;
    }
    __syncthreads();
    float inv = 1.f / sh_sum;

    for (int t = tid; t < T; t += NT)
        probs[(size_t)bh * T + t] = s[t] * inv;

    // ---- V phase: 16 groups of 16 lanes, float4, 4 rows in flight ----
    int g = tid >> 4, vl = tid & 15;
    const float4* Vb = reinterpret_cast<const float4*>(Vc + base) + vl;
    float4 a0 = make_float4(0.f,0.f,0.f,0.f), a1 = a0, a2 = a0, a3 = a0;
    int t = g;
    for (; t + 48 < Tc; t += 64) {
        float4 v0 = Vb[(size_t)t * 16];
        float4 v1 = Vb[(size_t)(t + 16) * 16];
        float4 v2 = Vb[(size_t)(t + 32) * 16];
        float4 v3 = Vb[(size_t)(t + 48) * 16];
        float w0 = s[t], w1 = s[t + 16], w2 = s[t + 32], w3 = s[t + 48];
        a0.x += w0 * v0.x; a0.y += w0 * v0.y; a0.z += w0 * v0.z; a0.w += w0 * v0.w;
        a1.x += w1 * v1.x; a1.y += w1 * v1.y; a1.z += w1 * v1.z; a1.w += w1 * v1.w;
        a2.x += w2 * v2.x; a2.y += w2 * v2.y; a2.z += w2 * v2.z; a2.w += w2 * v2.w;
        a3.x += w3 * v3.x; a3.y += w3 * v3.y; a3.z += w3 * v3.z; a3.w += w3 * v3.w;
    }
    for (; t < Tc; t += 16) {
        float4 v0 = Vb[(size_t)t * 16];
        float w0 = s[t];
        a0.x += w0 * v0.x; a0.y += w0 * v0.y; a0.z += w0 * v0.z; a0.w += w0 * v0.w;
    }
    if (vnew && g == (Tc & 15)) {
        float4 vn = reinterpret_cast<const float4*>(vnew + (size_t)bh * 64)[vl];
        float w = s[Tc];
        a0.x += w * vn.x; a0.y += w * vn.y; a0.z += w * vn.z; a0.w += w * vn.w;
    }
    a0.x += a1.x + a2.x + a3.x;
    a0.y += a1.y + a2.y + a3.y;
    a0.z += a1.z + a2.z + a3.z;
    a0.w += a1.w + a2.w + a3.w;
    red4[tid] = a0;
    __syncthreads();
    if (tid < 64) {
        const float* rf = reinterpret_cast<const float*>(red4);
        float tot = 0.f;
        #pragma unroll
        for (int gg = 0; gg < 16; gg++) tot += rf[gg * 64 + tid];
        outv[(size_t)b * 1024 + h * 64 + tid] = tot * inv;
    }
}

// ---------------- launcher ----------------
extern "C" void kernel_launch(void* const* d_in, const int* in_sizes, int n_in,
                              void* d_out, int out_size)
{
    const float* dec      = (const float*)d_in[0];
    const float* cache_k  = (const float*)d_in[1];
    const float* cache_v  = (const float*)d_in[2];
    const float* enc_k    = (const float*)d_in[3];
    const float* enc_v    = (const float*)d_in[4];
    const uint8_t* slfm   = (const uint8_t*)d_in[5];
    const uint8_t* encm   = (const uint8_t*)d_in[6];
    const float* w_qs_s   = (const float*)d_in[7];
    const float* w_ks_s   = (const float*)d_in[8];
    const float* w_vs_s   = (const float*)d_in[9];
    const float* proj_w_s = (const float*)d_in[10];
    const float* proj_b_s = (const float*)d_in[11];
    const float* ln_g_s   = (const float*)d_in[12];
    const float* ln_b_s   = (const float*)d_in[13];
    const float* w_qs_e   = (const float*)d_in[14];
    const float* proj_w_e = (const float*)d_in[15];
    const float* proj_b_e = (const float*)d_in[16];
    const float* ln_g_e   = (const float*)d_in[17];
    const float* ln_b_e   = (const float*)d_in[18];
    const float* ffn_w1   = (const float*)d_in[19];
    const float* ffn_b1   = (const float*)d_in[20];
    const float* ffn_w2   = (const float*)d_in[21];
    const float* ffn_b2   = (const float*)d_in[22];
    const float* ln_g_f   = (const float*)d_in[23];
    const float* ln_b_f   = (const float*)d_in[24];

    float* out = (float*)d_out;
    float* slf_probs = out + 32 * 1024;                 // [B,H,2048]
    float* enc_probs = slf_probs + 32 * 16 * 2048;      // [B,H,1024]

    float *pP, *pqkv, *pqe, *pas, *pae, *px1, *px2, *ph, *prow;
    cudaGetSymbolAddress((void**)&pP, g_P);
    cudaGetSymbolAddress((void**)&pqkv, g_qkv);
    cudaGetSymbolAddress((void**)&pqe, g_qe);
    cudaGetSymbolAddress((void**)&pas, g_attn_s);
    cudaGetSymbolAddress((void**)&pae, g_attn_e);
    cudaGetSymbolAddress((void**)&px1, g_x1);
    cudaGetSymbolAddress((void**)&px2, g_x2);
    cudaGetSymbolAddress((void**)&ph, g_h);
    cudaGetSymbolAddress((void**)&prow, g_row);
    float* pqs   = pqkv;
    float* pknew = pqkv + 32768;
    float* pvnew = pqkv + 65536;

    // fused q/k/v projections: 16 heads x 8 splits x 3 = 384 blocks
    gemm_qkv<<<dim3(16, 8, 3), NT>>>(dec, w_qs_s, w_ks_s, w_vs_s, pP);
    reduce_qkv<<<384, NT>>>(pP, pqkv);

    // self attention over cache + new token
    attn_kernel<<<512, NT>>>(pqs, cache_k, cache_v, pknew, pvnew, slfm,
                             slf_probs, pas, 2048, 2047);

    // proj + residual + LN  (16 n-tiles x 16 splits = 256 blocks)
    gemm_k64<<<dim3(16, 16), NT>>>(pas, proj_w_s, pP, 1024, 1024, 0);
    reduce_addres_t<<<128, NT>>>(pP, 16, proj_b_s, dec, prow);
    ln_norm<<<32, NT>>>(prow, ln_g_s, ln_b_s, px1);

    // cross-attn q projection (headed, 16 heads x 16 splits)
    gemm_k64<<<dim3(16, 16), NT>>>(px1, w_qs_e, pP, 1024, 1024, 1);
    reduce_sum_t<<<128, NT>>>(pP, pqe, 16);

    // cross attention
    attn_kernel<<<512, NT>>>(pqe, enc_k, enc_v, nullptr, nullptr, encm,
                             enc_probs, pae, 1024, 1024);

    // proj + residual + LN
    gemm_k64<<<dim3(16, 16), NT>>>(pae, proj_w_e, pP, 1024, 1024, 0);
    reduce_addres_t<<<128, NT>>>(pP, 16, proj_b_e, px1, prow);
    ln_norm<<<32, NT>>>(prow, ln_g_e, ln_b_e, px2);

    // FFN: w1 64 n-tiles x 8 splits = 512; w2 16 n-tiles x 32 splits = 512
    gemm_k128<<<dim3(64, 8), NT>>>(px2, ffn_w1, pP, 1024, 4096, 0);
    reduce_bias_relu_t<<<512, NT>>>(pP, ffn_b1, ph, 8);
    gemm_k128<<<dim3(16, 32), NT>>>(ph, ffn_w2, pP, 4096, 1024, 0);
    reduce_addres_t<<<128, NT>>>(pP, 32, ffn_b2, px2, prow);
    ln_norm<<<32, NT>>>(prow, ln_g_f, ln_b_f, out);
}

// round 15
// speedup vs baseline: 1.1974x; 1.1974x over previous
#include <cuda_runtime.h>
#include <math.h>
#include <stdint.h>

#define NT 256
#define NW 8

// ---------------- scratch (device globals, no allocation) ----------------
__device__ float g_P[4194304];     // split-K partials [slab][s][b][N]
__device__ float g_attn_s[32768];
__device__ float g_attn_e[32768];
__device__ float g_x1[32768];
__device__ float g_x2[32768];
__device__ float g_h[131072];      // ffn hidden [32,4096]

// ---------------- GEMM core (R12 config): C[32,N] = A[32,K] @ W ----------
// N-tile = 64 floats (16 float4 cols), 16 row-groups x 2 rows.
// A tile loaded to smem once, W streamed with 8-deep float4 prefetch.
// Partials row-major: P[bk][b][N].
// headed=1: W is [H][K][64] (n-tile == one head); headed=0: W is [K][N].
template<int KCHUNK>
__device__ __forceinline__ void gemm_core(const float* __restrict__ A,
                                          const float* __restrict__ W,
                                          float* __restrict__ P,
                                          int K, int N, int headed,
                                          int bn, int bk)
{
    __shared__ float As[32][KCHUNK];
    int tid = threadIdx.x, n4 = tid & 15, bg = tid >> 4;
    const float* Wt;
    size_t ldw;
    if (headed) { Wt = W + (size_t)bn * K * 64 + n4 * 4; ldw = 64; }
    else        { Wt = W + (size_t)bn * 64 + n4 * 4;     ldw = (size_t)N; }
    int k0 = bk * KCHUNK;

    #pragma unroll
    for (int i = tid; i < 32 * KCHUNK; i += NT) {
        int b = i / KCHUNK, kk = i % KCHUNK;
        As[b][kk] = A[(size_t)b * K + k0 + kk];
    }
    __syncthreads();

    float4 acc0 = make_float4(0.f, 0.f, 0.f, 0.f);
    float4 acc1 = make_float4(0.f, 0.f, 0.f, 0.f);
    const float* wp = Wt + (size_t)k0 * ldw;
    int r0 = bg * 2, r1 = bg * 2 + 1;

    #pragma unroll 4
    for (int kq = 0; kq < KCHUNK; kq += 8) {
        float4 w[8];
        #pragma unroll
        for (int j = 0; j < 8; j++)
            w[j] = *reinterpret_cast<const float4*>(wp + (size_t)(kq + j) * ldw);
        #pragma unroll
        for (int j = 0; j < 8; j++) {
            float a0 = As[r0][kq + j], a1 = As[r1][kq + j];
            acc0.x += a0 * w[j].x; acc0.y += a0 * w[j].y;
            acc0.z += a0 * w[j].z; acc0.w += a0 * w[j].w;
            acc1.x += a1 * w[j].x; acc1.y += a1 * w[j].y;
            acc1.z += a1 * w[j].z; acc1.w += a1 * w[j].w;
        }
    }
    float* dst = P + ((size_t)bk * 32 + r0) * N + (size_t)bn * 64 + n4 * 4;
    *reinterpret_cast<float4*>(dst)     = acc0;
    *reinterpret_cast<float4*>(dst + N) = acc1;
}

__global__ void __launch_bounds__(NT, 3)
gemm_k64(const float* __restrict__ A, const float* __restrict__ W,
         float* __restrict__ P, int K, int N, int headed)
{
    gemm_core<64>(A, W, P, K, N, headed, blockIdx.x, blockIdx.y);
}

__global__ void __launch_bounds__(NT, 3)
gemm_k128(const float* __restrict__ A, const float* __restrict__ W,
          float* __restrict__ P, int K, int N, int headed)
{
    gemm_core<128>(A, W, P, K, N, headed, blockIdx.x, blockIdx.y);
}

// fused q/k/v: z selects weight & partial slab (8 splits x 32768 each).
__global__ void __launch_bounds__(NT, 3)
gemm_qkv(const float* __restrict__ A,
         const float* __restrict__ W0,
         const float* __restrict__ W1,
         const float* __restrict__ W2,
         float* __restrict__ P)
{
    int z = blockIdx.z;
    const float* W = (z == 0) ? W0 : (z == 1) ? W1 : W2;
    gemm_core<128>(A, W, P + (size_t)z * 262144, 1024, 1024, 1,
                   blockIdx.x, blockIdx.y);
}

// ffn1 reduce: P[s][b][4096] -> relu(bias + sum)
__global__ void reduce_bias_relu(const float* __restrict__ P,
                                 const float* __restrict__ bias,
                                 float* __restrict__ out, int KS)
{
    int i = blockIdx.x * blockDim.x + threadIdx.x;   // 131072
    int b = i >> 12, c = i & 4095;
    const float* p = P + (size_t)b * 4096 + c;
    float v = bias[c];
    for (int s = 0; s < KS; s++) v += p[(size_t)s * 131072];
    out[i] = fmaxf(v, 0.f);
}

// ---------------- sum partials + bias + residual, then LayerNorm ----------
__global__ void ln_finish(const float* __restrict__ P, int KS,
                          const float* __restrict__ bias, const float* __restrict__ res,
                          const float* __restrict__ gam, const float* __restrict__ bet,
                          float* __restrict__ out)
{
    __shared__ float row[1024];
    __shared__ float redm[NW], redv[NW];
    __shared__ float sh_mean, sh_rstd;
    int b = blockIdx.x, tid = threadIdx.x, lane = tid & 31, wid = tid >> 5;
    float lsum = 0.f, lsq = 0.f;
    for (int c = tid; c < 1024; c += NT) {
        float v = bias[c] + res[(size_t)b * 1024 + c];
        const float* p = P + (size_t)b * 1024 + c;
        for (int s2 = 0; s2 < KS; s2++) v += p[(size_t)s2 * 32768];
        row[c] = v;
        lsum += v; lsq += v * v;
    }
    #pragma unroll
    for (int o = 16; o; o >>= 1) {
        lsum += __shfl_xor_sync(0xffffffffu, lsum, o);
        lsq  += __shfl_xor_sync(0xffffffffu, lsq, o);
    }
    if (!lane) { redm[wid] = lsum; redv[wid] = lsq; }
    __syncthreads();
    if (wid == 0) {
        float a  = (lane < NW) ? redm[lane] : 0.f;
        float c2 = (lane < NW) ? redv[lane] : 0.f;
        #pragma unroll
        for (int o = 4; o; o >>= 1) {
            a  += __shfl_xor_sync(0xffffffffu, a, o);
            c2 += __shfl_xor_sync(0xffffffffu, c2, o);
        }
        if (!lane) {
            float mean = a * (1.f / 1024.f);
            float var  = c2 * (1.f / 1024.f) - mean * mean;
            sh_mean = mean;
            sh_rstd = rsqrtf(var + 1e-6f);
        }
    }
    __syncthreads();
    float mean = sh_mean, rstd = sh_rstd;
    for (int c = tid; c < 1024; c += NT)
        out[(size_t)b * 1024 + c] = (row[c] - mean) * rstd * gam[c] + bet[c];
}

// ---------------- attention with fused split-K reduce of q (and k/v new) --
// qP: partials [qKS][32][1024]; kP/vP (optional): same layout, kvKS splits.
__global__ void attn_kernel(const float* __restrict__ qP, int qKS,
                            const float* __restrict__ Kc,
                            const float* __restrict__ Vc,
                            const float* __restrict__ kP,
                            const float* __restrict__ vP, int kvKS,
                            const uint8_t* __restrict__ mask,
                            float* __restrict__ probs,
                            float* __restrict__ outv,
                            int T, int Tc)
{
    __shared__ float s[2048];
    __shared__ float red[NW];
    __shared__ float4 red4[256];
    __shared__ float sh_max, sh_sum;
    int bh = blockIdx.x, b = bh >> 4, h = bh & 15;
    int tid = threadIdx.x, lane = tid & 31, wid = tid >> 5;
    size_t base = (size_t)bh * Tc * 64;
    const uint8_t* mrow = mask + (size_t)b * T;

    // ---- fused q reduce: q4 = sum over split-K partials ----
    float4 q4 = make_float4(0.f, 0.f, 0.f, 0.f);
    {
        const float* qb = qP + (size_t)b * 1024 + h * 64 + (lane & 15) * 4;
        for (int ss = 0; ss < qKS; ss++) {
            float4 t4 = *reinterpret_cast<const float4*>(qb + (size_t)ss * 32768);
            q4.x += t4.x; q4.y += t4.y; q4.z += t4.z; q4.w += t4.w;
        }
    }

    // ---- K phase: warp covers 2 rows per float4 load, 8 rows in flight ----
    float lmax = -INFINITY;
    int half = lane >> 4;
    for (int t0 = wid * 8; t0 < Tc; t0 += NW * 8) {
        float d[4];
        #pragma unroll
        for (int j = 0; j < 4; j++) {
            int r = t0 + 2 * j;
            float4 kv = make_float4(0.f, 0.f, 0.f, 0.f);
            if (r + half < Tc)
                kv = reinterpret_cast<const float4*>(Kc + base + (size_t)r * 64)[lane];
            d[j] = kv.x * q4.x + kv.y * q4.y + kv.z * q4.z + kv.w * q4.w;
        }
        #pragma unroll
        for (int j = 0; j < 4; j++) {
            float v = d[j];
            v += __shfl_xor_sync(0xffffffffu, v, 8);
            v += __shfl_xor_sync(0xffffffffu, v, 4);
            v += __shfl_xor_sync(0xffffffffu, v, 2);
            v += __shfl_xor_sync(0xffffffffu, v, 1);
            int r = t0 + 2 * j + half;
            if ((lane & 15) == 0 && r < Tc) {
                float sc = v * 0.125f;
                if (mrow[r]) sc = -INFINITY;
                s[r] = sc;
                lmax = fmaxf(lmax, sc);
            }
        }
    }
    // ---- new-token key (self-attn only): fused reduce of k partials ----
    if (kP && wid == 0) {
        const float* kb = kP + (size_t)b * 1024 + h * 64 + (lane & 15) * 4;
        float4 kv = make_float4(0.f, 0.f, 0.f, 0.f);
        for (int ss = 0; ss < kvKS; ss++) {
            float4 t4 = *reinterpret_cast<const float4*>(kb + (size_t)ss * 32768);
            kv.x += t4.x; kv.y += t4.y; kv.z += t4.z; kv.w += t4.w;
        }
        float v = kv.x * q4.x + kv.y * q4.y + kv.z * q4.z + kv.w * q4.w;
        v += __shfl_xor_sync(0xffffffffu, v, 8);
        v += __shfl_xor_sync(0xffffffffu, v, 4);
        v += __shfl_xor_sync(0xffffffffu, v, 2);
        v += __shfl_xor_sync(0xffffffffu, v, 1);
        if (lane == 0) {
            float sc = v * 0.125f;
            if (mrow[Tc]) sc = -INFINITY;
            s[Tc] = sc;
            lmax = fmaxf(lmax, sc);
        }
    }
    #pragma unroll
    for (int o = 16; o; o >>= 1) lmax = fmaxf(lmax, __shfl_xor_sync(0xffffffffu, lmax, o));
    if (lane == 0) red[wid] = lmax;
    __syncthreads();
    if (wid == 0) {
        float m = (lane < NW) ? red[lane] : -INFINITY;
        #pragma unroll
        for (int o = 4; o; o >>= 1) m = fmaxf(m, __shfl_xor_sync(0xffffffffu, m, o));
        if (lane == 0) sh_max = m;
    }
    __syncthreads();
    float gmax = sh_max;

    float lsum = 0.f;
    for (int t = tid; t < T; t += NT) {
        float e = __expf(s[t] - gmax);
        s[t] = e;
        lsum += e;
    }
    #pragma unroll
    for (int o = 16; o; o >>= 1) lsum += __shfl_xor_sync(0xffffffffu, lsum, o);
    if (lane == 0) red[wid] = lsum;
    __syncthreads();
    if (wid == 0) {
        float m = (lane < NW) ? red[lane] : 0.f;
        #pragma unroll
        for (int o = 4; o; o >>= 1) m += __shfl_xor_sync(0xffffffffu, m, o);
        if (lane == 0) sh_sum = m;
    }
    __syncthreads();
    float inv = 1.f / sh_sum;

    for (int t = tid; t < T; t += NT)
        probs[(size_t)bh * T + t] = s[t] * inv;

    // ---- V phase: 16 groups of 16 lanes, float4, 4 rows in flight ----
    int g = tid >> 4, vl = tid & 15;
    const float4* Vb = reinterpret_cast<const float4*>(Vc + base) + vl;
    float4 a0 = make_float4(0.f,0.f,0.f,0.f), a1 = a0, a2 = a0, a3 = a0;
    int t = g;
    for (; t + 48 < Tc; t += 64) {
        float4 v0 = Vb[(size_t)t * 16];
        float4 v1 = Vb[(size_t)(t + 16) * 16];
        float4 v2 = Vb[(size_t)(t + 32) * 16];
        float4 v3 = Vb[(size_t)(t + 48) * 16];
        float w0 = s[t], w1 = s[t + 16], w2 = s[t + 32], w3 = s[t + 48];
        a0.x += w0 * v0.x; a0.y += w0 * v0.y; a0.z += w0 * v0.z; a0.w += w0 * v0.w;
        a1.x += w1 * v1.x; a1.y += w1 * v1.y; a1.z += w1 * v1.z; a1.w += w1 * v1.w;
        a2.x += w2 * v2.x; a2.y += w2 * v2.y; a2.z += w2 * v2.z; a2.w += w2 * v2.w;
        a3.x += w3 * v3.x; a3.y += w3 * v3.y; a3.z += w3 * v3.z; a3.w += w3 * v3.w;
    }
    for (; t < Tc; t += 16) {
        float4 v0 = Vb[(size_t)t * 16];
        float w0 = s[t];
        a0.x += w0 * v0.x; a0.y += w0 * v0.y; a0.z += w0 * v0.z; a0.w += w0 * v0.w;
    }
    if (vP && g == (Tc & 15)) {
        const float* vb = vP + (size_t)b * 1024 + h * 64 + vl * 4;
        float4 vn = make_float4(0.f, 0.f, 0.f, 0.f);
        for (int ss = 0; ss < kvKS; ss++) {
            float4 t4 = *reinterpret_cast<const float4*>(vb + (size_t)ss * 32768);
            vn.x += t4.x; vn.y += t4.y; vn.z += t4.z; vn.w += t4.w;
        }
        float w = s[Tc];
        a0.x += w * vn.x; a0.y += w * vn.y; a0.z += w * vn.z; a0.w += w * vn.w;
    }
    a0.x += a1.x + a2.x + a3.x;
    a0.y += a1.y + a2.y + a3.y;
    a0.z += a1.z + a2.z + a3.z;
    a0.w += a1.w + a2.w + a3.w;
    red4[tid] = a0;
    __syncthreads();
    if (tid < 64) {
        const float* rf = reinterpret_cast<const float*>(red4);
        float tot = 0.f;
        #pragma unroll
        for (int gg = 0; gg < 16; gg++) tot += rf[gg * 64 + tid];
        outv[(size_t)b * 1024 + h * 64 + tid] = tot * inv;
    }
}

// ---------------- launcher ----------------
extern "C" void kernel_launch(void* const* d_in, const int* in_sizes, int n_in,
                              void* d_out, int out_size)
{
    const float* dec      = (const float*)d_in[0];
    const float* cache_k  = (const float*)d_in[1];
    const float* cache_v  = (const float*)d_in[2];
    const float* enc_k    = (const float*)d_in[3];
    const float* enc_v    = (const float*)d_in[4];
    const uint8_t* slfm   = (const uint8_t*)d_in[5];
    const uint8_t* encm   = (const uint8_t*)d_in[6];
    const float* w_qs_s   = (const float*)d_in[7];
    const float* w_ks_s   = (const float*)d_in[8];
    const float* w_vs_s   = (const float*)d_in[9];
    const float* proj_w_s = (const float*)d_in[10];
    const float* proj_b_s = (const float*)d_in[11];
    const float* ln_g_s   = (const float*)d_in[12];
    const float* ln_b_s   = (const float*)d_in[13];
    const float* w_qs_e   = (const float*)d_in[14];
    const float* proj_w_e = (const float*)d_in[15];
    const float* proj_b_e = (const float*)d_in[16];
    const float* ln_g_e   = (const float*)d_in[17];
    const float* ln_b_e   = (const float*)d_in[18];
    const float* ffn_w1   = (const float*)d_in[19];
    const float* ffn_b1   = (const float*)d_in[20];
    const float* ffn_w2   = (const float*)d_in[21];
    const float* ffn_b2   = (const float*)d_in[22];
    const float* ln_g_f   = (const float*)d_in[23];
    const float* ln_b_f   = (const float*)d_in[24];

    float* out = (float*)d_out;
    float* slf_probs = out + 32 * 1024;                 // [B,H,2048]
    float* enc_probs = slf_probs + 32 * 16 * 2048;      // [B,H,1024]

    float *pP, *pas, *pae, *px1, *px2, *ph;
    cudaGetSymbolAddress((void**)&pP, g_P);
    cudaGetSymbolAddress((void**)&pas, g_attn_s);
    cudaGetSymbolAddress((void**)&pae, g_attn_e);
    cudaGetSymbolAddress((void**)&px1, g_x1);
    cudaGetSymbolAddress((void**)&px2, g_x2);
    cudaGetSymbolAddress((void**)&ph, g_h);

    // 1. fused q/k/v projections: 3 slabs of 8 splits (partials in pP)
    gemm_qkv<<<dim3(16, 8, 3), NT>>>(dec, w_qs_s, w_ks_s, w_vs_s, pP);

    // 2. self attention (fused q/k/v split-K reduce inside)
    attn_kernel<<<512, NT>>>(pP, 8, cache_k, cache_v,
                             pP + 262144, pP + 524288, 8, slfm,
                             slf_probs, pas, 2048, 2047);

    // 3-4. proj + residual + LN
    gemm_k64<<<dim3(16, 16), NT>>>(pas, proj_w_s, pP, 1024, 1024, 0);
    ln_finish<<<32, NT>>>(pP, 16, proj_b_s, dec, ln_g_s, ln_b_s, px1);

    // 5. cross-attn q projection (headed)
    gemm_k64<<<dim3(16, 16), NT>>>(px1, w_qs_e, pP, 1024, 1024, 1);

    // 6. cross attention (fused q reduce inside)
    attn_kernel<<<512, NT>>>(pP, 16, enc_k, enc_v,
                             nullptr, nullptr, 0, encm,
                             enc_probs, pae, 1024, 1024);

    // 7-8. proj + residual + LN
    gemm_k64<<<dim3(16, 16), NT>>>(pae, proj_w_e, pP, 1024, 1024, 0);
    ln_finish<<<32, NT>>>(pP, 16, proj_b_e, px1, ln_g_e, ln_b_e, px2);

    // 9-10. FFN1 + bias/relu reduce
    gemm_k128<<<dim3(64, 8), NT>>>(px2, ffn_w1, pP, 1024, 4096, 0);
    reduce_bias_relu<<<512, NT>>>(pP, ffn_b1, ph, 8);

    // 11-12. FFN2 + residual + LN
    gemm_k128<<<dim3(16, 32), NT>>>(ph, ffn_w2, pP, 4096, 1024, 0);
    ln_finish<<<32, NT>>>(pP, 32, ffn_b2, px2, ln_g_f, ln_b_f, out);
}

// round 16
// speedup vs baseline: 1.2744x; 1.0642x over previous
#include <cuda_runtime.h>
#include <math.h>
#include <stdint.h>

#define NT 256
#define NW 8

// ---------------- scratch (device globals, no allocation) ----------------
__device__ float g_P[4194304];     // split-K partials [slab][s][b][N]
__device__ float g_attn_s[32768];
__device__ float g_attn_e[32768];
__device__ float g_x1[32768];
__device__ float g_x2[32768];
__device__ float g_h[131072];      // ffn hidden [32,4096]

// ---------------- GEMM core: C[32,N] = A[32,K] @ W, split-K partials ----
// N-tile = 64 floats (16 float4 cols), 16 row-groups x 2 rows.
// A tile loaded to smem once, W streamed with 8-deep float4 prefetch.
// headed=1: W is [H][K][64] (n-tile == one head); headed=0: W is [K][N].
template<int KCHUNK>
__device__ __forceinline__ void gemm_core(const float* __restrict__ A,
                                          const float* __restrict__ W,
                                          float* __restrict__ P,
                                          int K, int N, int headed,
                                          int bn, int bk)
{
    __shared__ float As[32][KCHUNK];
    int tid = threadIdx.x, n4 = tid & 15, bg = tid >> 4;
    const float* Wt;
    size_t ldw;
    if (headed) { Wt = W + (size_t)bn * K * 64 + n4 * 4; ldw = 64; }
    else        { Wt = W + (size_t)bn * 64 + n4 * 4;     ldw = (size_t)N; }
    int k0 = bk * KCHUNK;

    #pragma unroll
    for (int i = tid; i < 32 * KCHUNK; i += NT) {
        int b = i / KCHUNK, kk = i % KCHUNK;
        As[b][kk] = A[(size_t)b * K + k0 + kk];
    }
    __syncthreads();

    float4 acc0 = make_float4(0.f, 0.f, 0.f, 0.f);
    float4 acc1 = make_float4(0.f, 0.f, 0.f, 0.f);
    const float* wp = Wt + (size_t)k0 * ldw;
    int r0 = bg * 2, r1 = bg * 2 + 1;

    #pragma unroll 4
    for (int kq = 0; kq < KCHUNK; kq += 8) {
        float4 w[8];
        #pragma unroll
        for (int j = 0; j < 8; j++)
            w[j] = *reinterpret_cast<const float4*>(wp + (size_t)(kq + j) * ldw);
        #pragma unroll
        for (int j = 0; j < 8; j++) {
            float a0 = As[r0][kq + j], a1 = As[r1][kq + j];
            acc0.x += a0 * w[j].x; acc0.y += a0 * w[j].y;
            acc0.z += a0 * w[j].z; acc0.w += a0 * w[j].w;
            acc1.x += a1 * w[j].x; acc1.y += a1 * w[j].y;
            acc1.z += a1 * w[j].z; acc1.w += a1 * w[j].w;
        }
    }
    float* dst = P + ((size_t)bk * 32 + r0) * N + (size_t)bn * 64 + n4 * 4;
    *reinterpret_cast<float4*>(dst)     = acc0;
    *reinterpret_cast<float4*>(dst + N) = acc1;
}

__global__ void __launch_bounds__(NT, 3)
gemm_k64(const float* __restrict__ A, const float* __restrict__ W,
         float* __restrict__ P, int K, int N, int headed)
{
    gemm_core<64>(A, W, P, K, N, headed, blockIdx.x, blockIdx.y);
}

__global__ void __launch_bounds__(NT, 3)
gemm_k128(const float* __restrict__ A, const float* __restrict__ W,
          float* __restrict__ P, int K, int N, int headed)
{
    gemm_core<128>(A, W, P, K, N, headed, blockIdx.x, blockIdx.y);
}

// fused q/k/v: z selects weight & partial slab (8 splits x 32768 each).
__global__ void __launch_bounds__(NT, 3)
gemm_qkv(const float* __restrict__ A,
         const float* __restrict__ W0,
         const float* __restrict__ W1,
         const float* __restrict__ W2,
         float* __restrict__ P)
{
    int z = blockIdx.z;
    const float* W = (z == 0) ? W0 : (z == 1) ? W1 : W2;
    gemm_core<128>(A, W, P + (size_t)z * 262144, 1024, 1024, 1,
                   blockIdx.x, blockIdx.y);
}

// ffn1 reduce: P[s][b][4096] -> relu(bias + sum). float4, unrolled KS.
template<int KS>
__global__ void reduce_bias_relu(const float4* __restrict__ P,
                                 const float4* __restrict__ bias,
                                 float4* __restrict__ out)
{
    int i4 = blockIdx.x * blockDim.x + threadIdx.x;   // 32768 float4s
    int c4 = i4 & 1023;                                // 4096/4 per row
    float4 v = bias[c4];
    const float4* p = P + i4;
    #pragma unroll
    for (int s = 0; s < KS; s++) {
        float4 t = p[(size_t)s * 32768];
        v.x += t.x; v.y += t.y; v.z += t.z; v.w += t.w;
    }
    out[i4] = make_float4(fmaxf(v.x, 0.f), fmaxf(v.y, 0.f),
                          fmaxf(v.z, 0.f), fmaxf(v.w, 0.f));
}

// ---------------- sum partials + bias + residual, then LayerNorm ----------
// One block per batch row; thread t owns float4 column t (256*4 = 1024).
// KS independent float4 loads -> high MLP, no serial scalar chain.
template<int KS>
__global__ void ln_finish(const float4* __restrict__ P,
                          const float4* __restrict__ bias,
                          const float4* __restrict__ res,
                          const float4* __restrict__ gam,
                          const float4* __restrict__ bet,
                          float4* __restrict__ out)
{
    __shared__ float redm[NW], redv[NW];
    __shared__ float sh_mean, sh_rstd;
    int b = blockIdx.x, tid = threadIdx.x, lane = tid & 31, wid = tid >> 5;

    float4 v = bias[tid];
    float4 r = res[(size_t)b * 256 + tid];
    v.x += r.x; v.y += r.y; v.z += r.z; v.w += r.w;
    const float4* p = P + (size_t)b * 256 + tid;
    #pragma unroll
    for (int s = 0; s < KS; s++) {
        float4 t = p[(size_t)s * 8192];            // 32768 floats = 8192 float4
        v.x += t.x; v.y += t.y; v.z += t.z; v.w += t.w;
    }

    float lsum = (v.x + v.y) + (v.z + v.w);
    float lsq  = (v.x * v.x + v.y * v.y) + (v.z * v.z + v.w * v.w);
    #pragma unroll
    for (int o = 16; o; o >>= 1) {
        lsum += __shfl_xor_sync(0xffffffffu, lsum, o);
        lsq  += __shfl_xor_sync(0xffffffffu, lsq, o);
    }
    if (!lane) { redm[wid] = lsum; redv[wid] = lsq; }
    __syncthreads();
    if (wid == 0) {
        float a  = (lane < NW) ? redm[lane] : 0.f;
        float c2 = (lane < NW) ? redv[lane] : 0.f;
        #pragma unroll
        for (int o = 4; o; o >>= 1) {
            a  += __shfl_xor_sync(0xffffffffu, a, o);
            c2 += __shfl_xor_sync(0xffffffffu, c2, o);
        }
        if (!lane) {
            float mean = a * (1.f / 1024.f);
            float var  = c2 * (1.f / 1024.f) - mean * mean;
            sh_mean = mean;
            sh_rstd = rsqrtf(var + 1e-6f);
        }
    }
    __syncthreads();
    float mean = sh_mean, rstd = sh_rstd;
    float4 g = gam[tid], be = bet[tid];
    float4 o4;
    o4.x = (v.x - mean) * rstd * g.x + be.x;
    o4.y = (v.y - mean) * rstd * g.y + be.y;
    o4.z = (v.z - mean) * rstd * g.z + be.z;
    o4.w = (v.w - mean) * rstd * g.w + be.w;
    out[(size_t)b * 256 + tid] = o4;
}

// ---------------- attention with fused split-K reduce of q (and k/v new) --
__global__ void attn_kernel(const float* __restrict__ qP, int qKS,
                            const float* __restrict__ Kc,
                            const float* __restrict__ Vc,
                            const float* __restrict__ kP,
                            const float* __restrict__ vP, int kvKS,
                            const uint8_t* __restrict__ mask,
                            float* __restrict__ probs,
                            float* __restrict__ outv,
                            int T, int Tc)
{
    __shared__ float s[2048];
    __shared__ float red[NW];
    __shared__ float4 red4[256];
    __shared__ float sh_max, sh_sum;
    int bh = blockIdx.x, b = bh >> 4, h = bh & 15;
    int tid = threadIdx.x, lane = tid & 31, wid = tid >> 5;
    size_t base = (size_t)bh * Tc * 64;
    const uint8_t* mrow = mask + (size_t)b * T;

    // ---- fused q reduce ----
    float4 q4 = make_float4(0.f, 0.f, 0.f, 0.f);
    {
        const float* qb = qP + (size_t)b * 1024 + h * 64 + (lane & 15) * 4;
        for (int ss = 0; ss < qKS; ss++) {
            float4 t4 = *reinterpret_cast<const float4*>(qb + (size_t)ss * 32768);
            q4.x += t4.x; q4.y += t4.y; q4.z += t4.z; q4.w += t4.w;
        }
    }

    // ---- K phase ----
    float lmax = -INFINITY;
    int half = lane >> 4;
    for (int t0 = wid * 8; t0 < Tc; t0 += NW * 8) {
        float d[4];
        #pragma unroll
        for (int j = 0; j < 4; j++) {
            int r = t0 + 2 * j;
            float4 kv = make_float4(0.f, 0.f, 0.f, 0.f);
            if (r + half < Tc)
                kv = reinterpret_cast<const float4*>(Kc + base + (size_t)r * 64)[lane];
            d[j] = kv.x * q4.x + kv.y * q4.y + kv.z * q4.z + kv.w * q4.w;
        }
        #pragma unroll
        for (int j = 0; j < 4; j++) {
            float v = d[j];
            v += __shfl_xor_sync(0xffffffffu, v, 8);
            v += __shfl_xor_sync(0xffffffffu, v, 4);
            v += __shfl_xor_sync(0xffffffffu, v, 2);
            v += __shfl_xor_sync(0xffffffffu, v, 1);
            int r = t0 + 2 * j + half;
            if ((lane & 15) == 0 && r < Tc) {
                float sc = v * 0.125f;
                if (mrow[r]) sc = -INFINITY;
                s[r] = sc;
                lmax = fmaxf(lmax, sc);
            }
        }
    }
    if (kP && wid == 0) {
        const float* kb = kP + (size_t)b * 1024 + h * 64 + (lane & 15) * 4;
        float4 kv = make_float4(0.f, 0.f, 0.f, 0.f);
        for (int ss = 0; ss < kvKS; ss++) {
            float4 t4 = *reinterpret_cast<const float4*>(kb + (size_t)ss * 32768);
            kv.x += t4.x; kv.y += t4.y; kv.z += t4.z; kv.w += t4.w;
        }
        float v = kv.x * q4.x + kv.y * q4.y + kv.z * q4.z + kv.w * q4.w;
        v += __shfl_xor_sync(0xffffffffu, v, 8);
        v += __shfl_xor_sync(0xffffffffu, v, 4);
        v += __shfl_xor_sync(0xffffffffu, v, 2);
        v += __shfl_xor_sync(0xffffffffu, v, 1);
        if (lane == 0) {
            float sc = v * 0.125f;
            if (mrow[Tc]) sc = -INFINITY;
            s[Tc] = sc;
            lmax = fmaxf(lmax, sc);
        }
    }
    #pragma unroll
    for (int o = 16; o; o >>= 1) lmax = fmaxf(lmax, __shfl_xor_sync(0xffffffffu, lmax, o));
    if (lane == 0) red[wid] = lmax;
    __syncthreads();
    if (wid == 0) {
        float m = (lane < NW) ? red[lane] : -INFINITY;
        #pragma unroll
        for (int o = 4; o; o >>= 1) m = fmaxf(m, __shfl_xor_sync(0xffffffffu, m, o));
        if (lane == 0) sh_max = m;
    }
    __syncthreads();
    float gmax = sh_max;

    float lsum = 0.f;
    for (int t = tid; t < T; t += NT) {
        float e = __expf(s[t] - gmax);
        s[t] = e;
        lsum += e;
    }
    #pragma unroll
    for (int o = 16; o; o >>= 1) lsum += __shfl_xor_sync(0xffffffffu, lsum, o);
    if (lane == 0) red[wid] = lsum;
    __syncthreads();
    if (wid == 0) {
        float m = (lane < NW) ? red[lane] : 0.f;
        #pragma unroll
        for (int o = 4; o; o >>= 1) m += __shfl_xor_sync(0xffffffffu, m, o);
        if (lane == 0) sh_sum = m;
    }
    __syncthreads();
    float inv = 1.f / sh_sum;

    for (int t = tid; t < T; t += NT)
        probs[(size_t)bh * T + t] = s[t] * inv;

    // ---- V phase ----
    int g = tid >> 4, vl = tid & 15;
    const float4* Vb = reinterpret_cast<const float4*>(Vc + base) + vl;
    float4 a0 = make_float4(0.f,0.f,0.f,0.f), a1 = a0, a2 = a0, a3 = a0;
    int t = g;
    for (; t + 48 < Tc; t += 64) {
        float4 v0 = Vb[(size_t)t * 16];
        float4 v1 = Vb[(size_t)(t + 16) * 16];
        float4 v2 = Vb[(size_t)(t + 32) * 16];
        float4 v3 = Vb[(size_t)(t + 48) * 16];
        float w0 = s[t], w1 = s[t + 16], w2 = s[t + 32], w3 = s[t + 48];
        a0.x += w0 * v0.x; a0.y += w0 * v0.y; a0.z += w0 * v0.z; a0.w += w0 * v0.w;
        a1.x += w1 * v1.x; a1.y += w1 * v1.y; a1.z += w1 * v1.z; a1.w += w1 * v1.w;
        a2.x += w2 * v2.x; a2.y += w2 * v2.y; a2.z += w2 * v2.z; a2.w += w2 * v2.w;
        a3.x += w3 * v3.x; a3.y += w3 * v3.y; a3.z += w3 * v3.z; a3.w += w3 * v3.w;
    }
    for (; t < Tc; t += 16) {
        float4 v0 = Vb[(size_t)t * 16];
        float w0 = s[t];
        a0.x += w0 * v0.x; a0.y += w0 * v0.y; a0.z += w0 * v0.z; a0.w += w0 * v0.w;
    }
    if (vP && g == (Tc & 15)) {
        const float* vb = vP + (size_t)b * 1024 + h * 64 + vl * 4;
        float4 vn = make_float4(0.f, 0.f, 0.f, 0.f);
        for (int ss = 0; ss < kvKS; ss++) {
            float4 t4 = *reinterpret_cast<const float4*>(vb + (size_t)ss * 32768);
            vn.x += t4.x; vn.y += t4.y; vn.z += t4.z; vn.w += t4.w;
        }
        float w = s[Tc];
        a0.x += w * vn.x; a0.y += w * vn.y; a0.z += w * vn.z; a0.w += w * vn.w;
    }
    a0.x += a1.x + a2.x + a3.x;
    a0.y += a1.y + a2.y + a3.y;
    a0.z += a1.z + a2.z + a3.z;
    a0.w += a1.w + a2.w + a3.w;
    red4[tid] = a0;
    __syncthreads();
    if (tid < 64) {
        const float* rf = reinterpret_cast<const float*>(red4);
        float tot = 0.f;
        #pragma unroll
        for (int gg = 0; gg < 16; gg++) tot += rf[gg * 64 + tid];
        outv[(size_t)b * 1024 + h * 64 + tid] = tot * inv;
    }
}

// ---------------- launcher ----------------
extern "C" void kernel_launch(void* const* d_in, const int* in_sizes, int n_in,
                              void* d_out, int out_size)
{
    const float* dec      = (const float*)d_in[0];
    const float* cache_k  = (const float*)d_in[1];
    const float* cache_v  = (const float*)d_in[2];
    const float* enc_k    = (const float*)d_in[3];
    const float* enc_v    = (const float*)d_in[4];
    const uint8_t* slfm   = (const uint8_t*)d_in[5];
    const uint8_t* encm   = (const uint8_t*)d_in[6];
    const float* w_qs_s   = (const float*)d_in[7];
    const float* w_ks_s   = (const float*)d_in[8];
    const float* w_vs_s   = (const float*)d_in[9];
    const float* proj_w_s = (const float*)d_in[10];
    const float* proj_b_s = (const float*)d_in[11];
    const float* ln_g_s   = (const float*)d_in[12];
    const float* ln_b_s   = (const float*)d_in[13];
    const float* w_qs_e   = (const float*)d_in[14];
    const float* proj_w_e = (const float*)d_in[15];
    const float* proj_b_e = (const float*)d_in[16];
    const float* ln_g_e   = (const float*)d_in[17];
    const float* ln_b_e   = (const float*)d_in[18];
    const float* ffn_w1   = (const float*)d_in[19];
    const float* ffn_b1   = (const float*)d_in[20];
    const float* ffn_w2   = (const float*)d_in[21];
    const float* ffn_b2   = (const float*)d_in[22];
    const float* ln_g_f   = (const float*)d_in[23];
    const float* ln_b_f   = (const float*)d_in[24];

    float* out = (float*)d_out;
    float* slf_probs = out + 32 * 1024;                 // [B,H,2048]
    float* enc_probs = slf_probs + 32 * 16 * 2048;      // [B,H,1024]

    float *pP, *pas, *pae, *px1, *px2, *ph;
    cudaGetSymbolAddress((void**)&pP, g_P);
    cudaGetSymbolAddress((void**)&pas, g_attn_s);
    cudaGetSymbolAddress((void**)&pae, g_attn_e);
    cudaGetSymbolAddress((void**)&px1, g_x1);
    cudaGetSymbolAddress((void**)&px2, g_x2);
    cudaGetSymbolAddress((void**)&ph, g_h);

    // 1. fused q/k/v projections
    gemm_qkv<<<dim3(16, 8, 3), NT>>>(dec, w_qs_s, w_ks_s, w_vs_s, pP);

    // 2. self attention (fused q/k/v split-K reduce inside)
    attn_kernel<<<512, NT>>>(pP, 8, cache_k, cache_v,
                             pP + 262144, pP + 524288, 8, slfm,
                             slf_probs, pas, 2048, 2047);

    // 3-4. proj + residual + LN
    gemm_k64<<<dim3(16, 16), NT>>>(pas, proj_w_s, pP, 1024, 1024, 0);
    ln_finish<16><<<32, NT>>>((const float4*)pP, (const float4*)proj_b_s,
                              (const float4*)dec, (const float4*)ln_g_s,
                              (const float4*)ln_b_s, (float4*)px1);

    // 5. cross-attn q projection (headed)
    gemm_k64<<<dim3(16, 16), NT>>>(px1, w_qs_e, pP, 1024, 1024, 1);

    // 6. cross attention (fused q reduce inside)
    attn_kernel<<<512, NT>>>(pP, 16, enc_k, enc_v,
                             nullptr, nullptr, 0, encm,
                             enc_probs, pae, 1024, 1024);

    // 7-8. proj + residual + LN
    gemm_k64<<<dim3(16, 16), NT>>>(pae, proj_w_e, pP, 1024, 1024, 0);
    ln_finish<16><<<32, NT>>>((const float4*)pP, (const float4*)proj_b_e,
                              (const float4*)px1, (const float4*)ln_g_e,
                              (const float4*)ln_b_e, (float4*)px2);

    // 9-10. FFN1 + bias/relu reduce
    gemm_k128<<<dim3(64, 8), NT>>>(px2, ffn_w1, pP, 1024, 4096, 0);
    reduce_bias_relu<8><<<128, NT>>>((const float4*)pP, (const float4*)ffn_b1,
                                     (float4*)ph);

    // 11-12. FFN2 + residual + LN
    gemm_k128<<<dim3(16, 32), NT>>>(ph, ffn_w2, pP, 4096, 1024, 0);
    ln_finish<32><<<32, NT>>>((const float4*)pP, (const float4*)ffn_b2,
                              (const float4*)px2, (const float4*)ln_g_f,
                              (const float4*)ln_b_f, (float4*)out);
}

// round 17
// speedup vs baseline: 1.2845x; 1.0079x over previous
#include <cuda_runtime.h>
#include <math.h>
#include <stdint.h>

#define NT 256
#define NW 8

// ---------------- scratch (device globals, no allocation) ----------------
__device__ float g_P[4194304];     // split-K partials [slab][s][b][N]
__device__ float g_attn_s[32768];
__device__ float g_attn_e[32768];
__device__ float g_x1[32768];
__device__ float g_x2[32768];
__device__ float g_h[131072];      // ffn hidden [32,4096]

// ---------------- GEMM core: C[32,N] = A[32,K] @ W, split-K partials ----
// N-tile = 64 floats (16 float4 cols), 16 row-groups x 2 rows.
// A tile loaded to smem once, W streamed with 8-deep float4 prefetch.
// headed=1: W is [H][K][64] (n-tile == one head); headed=0: W is [K][N].
template<int KCHUNK>
__device__ __forceinline__ void gemm_core(const float* __restrict__ A,
                                          const float* __restrict__ W,
                                          float* __restrict__ P,
                                          int K, int N, int headed,
                                          int bn, int bk)
{
    __shared__ float As[32][KCHUNK];
    int tid = threadIdx.x, n4 = tid & 15, bg = tid >> 4;
    const float* Wt;
    size_t ldw;
    if (headed) { Wt = W + (size_t)bn * K * 64 + n4 * 4; ldw = 64; }
    else        { Wt = W + (size_t)bn * 64 + n4 * 4;     ldw = (size_t)N; }
    int k0 = bk * KCHUNK;

    #pragma unroll
    for (int i = tid; i < 32 * KCHUNK; i += NT) {
        int b = i / KCHUNK, kk = i % KCHUNK;
        As[b][kk] = A[(size_t)b * K + k0 + kk];
    }
    __syncthreads();

    float4 acc0 = make_float4(0.f, 0.f, 0.f, 0.f);
    float4 acc1 = make_float4(0.f, 0.f, 0.f, 0.f);
    const float* wp = Wt + (size_t)k0 * ldw;
    int r0 = bg * 2, r1 = bg * 2 + 1;

    #pragma unroll 4
    for (int kq = 0; kq < KCHUNK; kq += 8) {
        float4 w[8];
        #pragma unroll
        for (int j = 0; j < 8; j++)
            w[j] = *reinterpret_cast<const float4*>(wp + (size_t)(kq + j) * ldw);
        #pragma unroll
        for (int j = 0; j < 8; j++) {
            float a0 = As[r0][kq + j], a1 = As[r1][kq + j];
            acc0.x += a0 * w[j].x; acc0.y += a0 * w[j].y;
            acc0.z += a0 * w[j].z; acc0.w += a0 * w[j].w;
            acc1.x += a1 * w[j].x; acc1.y += a1 * w[j].y;
            acc1.z += a1 * w[j].z; acc1.w += a1 * w[j].w;
        }
    }
    float* dst = P + ((size_t)bk * 32 + r0) * N + (size_t)bn * 64 + n4 * 4;
    *reinterpret_cast<float4*>(dst)     = acc0;
    *reinterpret_cast<float4*>(dst + N) = acc1;
}

__global__ void __launch_bounds__(NT, 3)
gemm_k64(const float* __restrict__ A, const float* __restrict__ W,
         float* __restrict__ P, int K, int N, int headed)
{
    gemm_core<64>(A, W, P, K, N, headed, blockIdx.x, blockIdx.y);
}

__global__ void __launch_bounds__(NT, 3)
gemm_k128(const float* __restrict__ A, const float* __restrict__ W,
          float* __restrict__ P, int K, int N, int headed)
{
    gemm_core<128>(A, W, P, K, N, headed, blockIdx.x, blockIdx.y);
}

// fused q/k/v: z selects weight & partial slab (8 splits x 32768 each).
__global__ void __launch_bounds__(NT, 3)
gemm_qkv(const float* __restrict__ A,
         const float* __restrict__ W0,
         const float* __restrict__ W1,
         const float* __restrict__ W2,
         float* __restrict__ P)
{
    int z = blockIdx.z;
    const float* W = (z == 0) ? W0 : (z == 1) ? W1 : W2;
    gemm_core<128>(A, W, P + (size_t)z * 262144, 1024, 1024, 1,
                   blockIdx.x, blockIdx.y);
}

// ffn1 reduce: P[s][b][4096] -> relu(bias + sum). float4, unrolled KS.
template<int KS>
__global__ void reduce_bias_relu(const float4* __restrict__ P,
                                 const float4* __restrict__ bias,
                                 float4* __restrict__ out)
{
    int i4 = blockIdx.x * blockDim.x + threadIdx.x;   // 32768 float4s
    int c4 = i4 & 1023;                                // 4096/4 per row
    float4 v = bias[c4];
    const float4* p = P + i4;
    #pragma unroll
    for (int s = 0; s < KS; s++) {
        float4 t = p[(size_t)s * 32768];
        v.x += t.x; v.y += t.y; v.z += t.z; v.w += t.w;
    }
    out[i4] = make_float4(fmaxf(v.x, 0.f), fmaxf(v.y, 0.f),
                          fmaxf(v.z, 0.f), fmaxf(v.w, 0.f));
}

// ---------------- sum partials + bias + residual, then LayerNorm ----------
// One block per batch row; thread t owns float4 column t (256*4 = 1024).
// KS independent float4 loads -> high MLP, no serial scalar chain.
template<int KS>
__global__ void ln_finish(const float4* __restrict__ P,
                          const float4* __restrict__ bias,
                          const float4* __restrict__ res,
                          const float4* __restrict__ gam,
                          const float4* __restrict__ bet,
                          float4* __restrict__ out)
{
    __shared__ float redm[NW], redv[NW];
    __shared__ float sh_mean, sh_rstd;
    int b = blockIdx.x, tid = threadIdx.x, lane = tid & 31, wid = tid >> 5;

    float4 v = bias[tid];
    float4 r = res[(size_t)b * 256 + tid];
    v.x += r.x; v.y += r.y; v.z += r.z; v.w += r.w;
    const float4* p = P + (size_t)b * 256 + tid;
    #pragma unroll
    for (int s = 0; s < KS; s++) {
        float4 t = p[(size_t)s * 8192];            // 32768 floats = 8192 float4
        v.x += t.x; v.y += t.y; v.z += t.z; v.w += t.w;
    }

    float lsum = (v.x + v.y) + (v.z + v.w);
    float lsq  = (v.x * v.x + v.y * v.y) + (v.z * v.z + v.w * v.w);
    #pragma unroll
    for (int o = 16; o; o >>= 1) {
        lsum += __shfl_xor_sync(0xffffffffu, lsum, o);
        lsq  += __shfl_xor_sync(0xffffffffu, lsq, o);
    }
    if (!lane) { redm[wid] = lsum; redv[wid] = lsq; }
    __syncthreads();
    if (wid == 0) {
        float a  = (lane < NW) ? redm[lane] : 0.f;
        float c2 = (lane < NW) ? redv[lane] : 0.f;
        #pragma unroll
        for (int o = 4; o; o >>= 1) {
            a  += __shfl_xor_sync(0xffffffffu, a, o);
            c2 += __shfl_xor_sync(0xffffffffu, c2, o);
        }
        if (!lane) {
            float mean = a * (1.f / 1024.f);
            float var  = c2 * (1.f / 1024.f) - mean * mean;
            sh_mean = mean;
            sh_rstd = rsqrtf(var + 1e-6f);
        }
    }
    __syncthreads();
    float mean = sh_mean, rstd = sh_rstd;
    float4 g = gam[tid], be = bet[tid];
    float4 o4;
    o4.x = (v.x - mean) * rstd * g.x + be.x;
    o4.y = (v.y - mean) * rstd * g.y + be.y;
    o4.z = (v.z - mean) * rstd * g.z + be.z;
    o4.w = (v.w - mean) * rstd * g.w + be.w;
    out[(size_t)b * 256 + tid] = o4;
}

// ---------------- attention with fused split-K reduce of q (and k/v new) --
__global__ void attn_kernel(const float* __restrict__ qP, int qKS,
                            const float* __restrict__ Kc,
                            const float* __restrict__ Vc,
                            const float* __restrict__ kP,
                            const float* __restrict__ vP, int kvKS,
                            const uint8_t* __restrict__ mask,
                            float* __restrict__ probs,
                            float* __restrict__ outv,
                            int T, int Tc)
{
    __shared__ float s[2048];
    __shared__ float red[NW];
    __shared__ float4 red4[256];
    __shared__ float sh_max, sh_sum;
    int bh = blockIdx.x, b = bh >> 4, h = bh & 15;
    int tid = threadIdx.x, lane = tid & 31, wid = tid >> 5;
    size_t base = (size_t)bh * Tc * 64;
    const uint8_t* mrow = mask + (size_t)b * T;

    // ---- fused q reduce ----
    float4 q4 = make_float4(0.f, 0.f, 0.f, 0.f);
    {
        const float* qb = qP + (size_t)b * 1024 + h * 64 + (lane & 15) * 4;
        for (int ss = 0; ss < qKS; ss++) {
            float4 t4 = *reinterpret_cast<const float4*>(qb + (size_t)ss * 32768);
            q4.x += t4.x; q4.y += t4.y; q4.z += t4.z; q4.w += t4.w;
        }
    }

    // ---- K phase ----
    float lmax = -INFINITY;
    int half = lane >> 4;
    for (int t0 = wid * 8; t0 < Tc; t0 += NW * 8) {
        float d[4];
        #pragma unroll
        for (int j = 0; j < 4; j++) {
            int r = t0 + 2 * j;
            float4 kv = make_float4(0.f, 0.f, 0.f, 0.f);
            if (r + half < Tc)
                kv = reinterpret_cast<const float4*>(Kc + base + (size_t)r * 64)[lane];
            d[j] = kv.x * q4.x + kv.y * q4.y + kv.z * q4.z + kv.w * q4.w;
        }
        #pragma unroll
        for (int j = 0; j < 4; j++) {
            float v = d[j];
            v += __shfl_xor_sync(0xffffffffu, v, 8);
            v += __shfl_xor_sync(0xffffffffu, v, 4);
            v += __shfl_xor_sync(0xffffffffu, v, 2);
            v += __shfl_xor_sync(0xffffffffu, v, 1);
            int r = t0 + 2 * j + half;
            if ((lane & 15) == 0 && r < Tc) {
                float sc = v * 0.125f;
                if (mrow[r]) sc = -INFINITY;
                s[r] = sc;
                lmax = fmaxf(lmax, sc);
            }
        }
    }
    if (kP && wid == 0) {
        const float* kb = kP + (size_t)b * 1024 + h * 64 + (lane & 15) * 4;
        float4 kv = make_float4(0.f, 0.f, 0.f, 0.f);
        for (int ss = 0; ss < kvKS; ss++) {
            float4 t4 = *reinterpret_cast<const float4*>(kb + (size_t)ss * 32768);
            kv.x += t4.x; kv.y += t4.y; kv.z += t4.z; kv.w += t4.w;
        }
        float v = kv.x * q4.x + kv.y * q4.y + kv.z * q4.z + kv.w * q4.w;
        v += __shfl_xor_sync(0xffffffffu, v, 8);
        v += __shfl_xor_sync(0xffffffffu, v, 4);
        v += __shfl_xor_sync(0xffffffffu, v, 2);
        v += __shfl_xor_sync(0xffffffffu, v, 1);
        if (lane == 0) {
            float sc = v * 0.125f;
            if (mrow[Tc]) sc = -INFINITY;
            s[Tc] = sc;
            lmax = fmaxf(lmax, sc);
        }
    }
    #pragma unroll
    for (int o = 16; o; o >>= 1) lmax = fmaxf(lmax, __shfl_xor_sync(0xffffffffu, lmax, o));
    if (lane == 0) red[wid] = lmax;
    __syncthreads();
    if (wid == 0) {
        float m = (lane < NW) ? red[lane] : -INFINITY;
        #pragma unroll
        for (int o = 4; o; o >>= 1) m = fmaxf(m, __shfl_xor_sync(0xffffffffu, m, o));
        if (lane == 0) sh_max = m;
    }
    __syncthreads();
    float gmax = sh_max;

    float lsum = 0.f;
    for (int t = tid; t < T; t += NT) {
        float e = __expf(s[t] - gmax);
        s[t] = e;
        lsum += e;
    }
    #pragma unroll
    for (int o = 16; o; o >>= 1) lsum += __shfl_xor_sync(0xffffffffu, lsum, o);
    if (lane == 0) red[wid] = lsum;
    __syncthreads();
    if (wid == 0) {
        float m = (lane < NW) ? red[lane] : 0.f;
        #pragma unroll
        for (int o = 4; o; o >>= 1) m += __shfl_xor_sync(0xffffffffu, m, o);
        if (lane == 0) sh_sum = m;
    }
    __syncthreads();
    float inv = 1.f / sh_sum;

    for (int t = tid; t < T; t += NT)
        probs[(size_t)bh * T + t] = s[t] * inv;

    // ---- V phase ----
    int g = tid >> 4, vl = tid & 15;
    const float4* Vb = reinterpret_cast<const float4*>(Vc + base) + vl;
    float4 a0 = make_float4(0.f,0.f,0.f,0.f), a1 = a0, a2 = a0, a3 = a0;
    int t = g;
    for (; t + 48 < Tc; t += 64) {
        float4 v0 = Vb[(size_t)t * 16];
        float4 v1 = Vb[(size_t)(t + 16) * 16];
        float4 v2 = Vb[(size_t)(t + 32) * 16];
        float4 v3 = Vb[(size_t)(t + 48) * 16];
        float w0 = s[t], w1 = s[t + 16], w2 = s[t + 32], w3 = s[t + 48];
        a0.x += w0 * v0.x; a0.y += w0 * v0.y; a0.z += w0 * v0.z; a0.w += w0 * v0.w;
        a1.x += w1 * v1.x; a1.y += w1 * v1.y; a1.z += w1 * v1.z; a1.w += w1 * v1.w;
        a2.x += w2 * v2.x; a2.y += w2 * v2.y; a2.z += w2 * v2.z; a2.w += w2 * v2.w;
        a3.x += w3 * v3.x; a3.y += w3 * v3.y; a3.z += w3 * v3.z; a3.w += w3 * v3.w;
    }
    for (; t < Tc; t += 16) {
        float4 v0 = Vb[(size_t)t * 16];
        float w0 = s[t];
        a0.x += w0 * v0.x; a0.y += w0 * v0.y; a0.z += w0 * v0.z; a0.w += w0 * v0.w;
    }
    if (vP && g == (Tc & 15)) {
        const float* vb = vP + (size_t)b * 1024 + h * 64 + vl * 4;
        float4 vn = make_float4(0.f, 0.f, 0.f, 0.f);
        for (int ss = 0; ss < kvKS; ss++) {
            float4 t4 = *reinterpret_cast<const float4*>(vb + (size_t)ss * 32768);
            vn.x += t4.x; vn.y += t4.y; vn.z += t4.z; vn.w += t4.w;
        }
        float w = s[Tc];
        a0.x += w * vn.x; a0.y += w * vn.y; a0.z += w * vn.z; a0.w += w * vn.w;
    }
    a0.x += a1.x + a2.x + a3.x;
    a0.y += a1.y + a2.y + a3.y;
    a0.z += a1.z + a2.z + a3.z;
    a0.w += a1.w + a2.w + a3.w;
    red4[tid] = a0;
    __syncthreads();
    if (tid < 64) {
        const float* rf = reinterpret_cast<const float*>(red4);
        float tot = 0.f;
        #pragma unroll
        for (int gg = 0; gg < 16; gg++) tot += rf[gg * 64 + tid];
        outv[(size_t)b * 1024 + h * 64 + tid] = tot * inv;
    }
}

// ---------------- launcher ----------------
extern "C" void kernel_launch(void* const* d_in, const int* in_sizes, int n_in,
                              void* d_out, int out_size)
{
    const float* dec      = (const float*)d_in[0];
    const float* cache_k  = (const float*)d_in[1];
    const float* cache_v  = (const float*)d_in[2];
    const float* enc_k    = (const float*)d_in[3];
    const float* enc_v    = (const float*)d_in[4];
    const uint8_t* slfm   = (const uint8_t*)d_in[5];
    const uint8_t* encm   = (const uint8_t*)d_in[6];
    const float* w_qs_s   = (const float*)d_in[7];
    const float* w_ks_s   = (const float*)d_in[8];
    const float* w_vs_s   = (const float*)d_in[9];
    const float* proj_w_s = (const float*)d_in[10];
    const float* proj_b_s = (const float*)d_in[11];
    const float* ln_g_s   = (const float*)d_in[12];
    const float* ln_b_s   = (const float*)d_in[13];
    const float* w_qs_e   = (const float*)d_in[14];
    const float* proj_w_e = (const float*)d_in[15];
    const float* proj_b_e = (const float*)d_in[16];
    const float* ln_g_e   = (const float*)d_in[17];
    const float* ln_b_e   = (const float*)d_in[18];
    const float* ffn_w1   = (const float*)d_in[19];
    const float* ffn_b1   = (const float*)d_in[20];
    const float* ffn_w2   = (const float*)d_in[21];
    const float* ffn_b2   = (const float*)d_in[22];
    const float* ln_g_f   = (const float*)d_in[23];
    const float* ln_b_f   = (const float*)d_in[24];

    float* out = (float*)d_out;
    float* slf_probs = out + 32 * 1024;                 // [B,H,2048]
    float* enc_probs = slf_probs + 32 * 16 * 2048;      // [B,H,1024]

    float *pP, *pas, *pae, *px1, *px2, *ph;
    cudaGetSymbolAddress((void**)&pP, g_P);
    cudaGetSymbolAddress((void**)&pas, g_attn_s);
    cudaGetSymbolAddress((void**)&pae, g_attn_e);
    cudaGetSymbolAddress((void**)&px1, g_x1);
    cudaGetSymbolAddress((void**)&px2, g_x2);
    cudaGetSymbolAddress((void**)&ph, g_h);

    // 1. fused q/k/v projections
    gemm_qkv<<<dim3(16, 8, 3), NT>>>(dec, w_qs_s, w_ks_s, w_vs_s, pP);

    // 2. self attention (fused q/k/v split-K reduce inside)
    attn_kernel<<<512, NT>>>(pP, 8, cache_k, cache_v,
                             pP + 262144, pP + 524288, 8, slfm,
                             slf_probs, pas, 2048, 2047);

    // 3-4. proj + residual + LN
    gemm_k64<<<dim3(16, 16), NT>>>(pas, proj_w_s, pP, 1024, 1024, 0);
    ln_finish<16><<<32, NT>>>((const float4*)pP, (const float4*)proj_b_s,
                              (const float4*)dec, (const float4*)ln_g_s,
                              (const float4*)ln_b_s, (float4*)px1);

    // 5. cross-attn q projection (headed)
    gemm_k64<<<dim3(16, 16), NT>>>(px1, w_qs_e, pP, 1024, 1024, 1);

    // 6. cross attention (fused q reduce inside)
    attn_kernel<<<512, NT>>>(pP, 16, enc_k, enc_v,
                             nullptr, nullptr, 0, encm,
                             enc_probs, pae, 1024, 1024);

    // 7-8. proj + residual + LN
    gemm_k64<<<dim3(16, 16), NT>>>(pae, proj_w_e, pP, 1024, 1024, 0);
    ln_finish<16><<<32, NT>>>((const float4*)pP, (const float4*)proj_b_e,
                              (const float4*)px1, (const float4*)ln_g_e,
                              (const float4*)ln_b_e, (float4*)px2);

    // 9-10. FFN1 + bias/relu reduce
    gemm_k128<<<dim3(64, 8), NT>>>(px2, ffn_w1, pP, 1024, 4096, 0);
    reduce_bias_relu<8><<<128, NT>>>((const float4*)pP, (const float4*)ffn_b1,
                                     (float4*)ph);

    // 11-12. FFN2 + residual + LN
    gemm_k128<<<dim3(16, 32), NT>>>(ph, ffn_w2, pP, 4096, 1024, 0);
    ln_finish<32><<<32, NT>>>((const float4*)pP, (const float4*)ffn_b2,
                              (const float4*)px2, (const float4*)ln_g_f,
                              (const float4*)ln_b_f, (float4*)out);
}